// round 16
// baseline (speedup 1.0000x reference)
#include <cuda_runtime.h>
#include <cuda_fp16.h>
#include <cstdint>

#define BB 64
#define NS 512
#define DS 300
#define DP 304                          // K padded to multiple of 16
#define BN_ROWS (BB*NS)                 // 32768
#define INV_SQRT_D 0.057735026918962576f
#define MASKED_CNORM (1.0f)

// ---------------------------------------------------------------------------
// Device-global scratch (runtime allocation forbidden); 16B-aligned rows.
// ---------------------------------------------------------------------------
__device__ alignas(1024) __half g_c_h[(size_t)BN_ROWS * DP];     // concepts fp16
__device__ alignas(1024) __half g_o_h[(size_t)BN_ROWS * DP];     // ocr fp16
__device__ alignas(1024) __half g_ct_h[(size_t)BB * DS * NS];    // concepts^T fp16
__device__ alignas(1024) __half g_wq_h[DS * DP];
__device__ alignas(1024) __half g_wk_h[DS * DP];
__device__ alignas(1024) __half g_Qh[(size_t)BN_ROWS * DP];
__device__ alignas(1024) __half g_Kh[(size_t)BN_ROWS * DP];
__device__ alignas(1024) __half g_Ph[(size_t)BB * NS * NS];
__device__ alignas(1024) float  g_A[(size_t)BB * NS * NS];       // scores fp32
__device__ alignas(1024) float  g_S[(size_t)BN_ROWS * DS];       // semantic fp32

// ---------------------------------------------------------------------------
// PTX helpers (sm_80-era only; compiles under compute_103)
// ---------------------------------------------------------------------------
__device__ __forceinline__ uint32_t smem_to_u32(const void* p) {
    uint32_t a;
    asm("{ .reg .u64 t; cvta.to.shared.u64 t, %1; cvt.u32.u64 %0, t; }" : "=r"(a) : "l"(p));
    return a;
}
__device__ __forceinline__ void cp_async16(uint32_t dst, const void* src) {
    asm volatile("cp.async.cg.shared.global [%0], [%1], 16;"
                 :: "r"(dst), "l"(src) : "memory");
}
#define CP_COMMIT() asm volatile("cp.async.commit_group;" ::: "memory")
#define CP_WAIT(n)  asm volatile("cp.async.wait_group %0;" :: "n"(n) : "memory")

__device__ __forceinline__ void ldsm_x4(uint32_t* r, uint32_t addr) {
    asm volatile("ldmatrix.sync.aligned.m8n8.x4.shared.b16 {%0,%1,%2,%3}, [%4];"
                 : "=r"(r[0]), "=r"(r[1]), "=r"(r[2]), "=r"(r[3]) : "r"(addr));
}
__device__ __forceinline__ void mma16816h(float* d, const uint32_t* a, const uint32_t* b) {
    asm volatile("mma.sync.aligned.m16n8k16.row.col.f32.f16.f16.f32 "
                 "{%0,%1,%2,%3}, {%4,%5,%6,%7}, {%8,%9}, {%0,%1,%2,%3};"
                 : "+f"(d[0]), "+f"(d[1]), "+f"(d[2]), "+f"(d[3])
                 : "r"(a[0]), "r"(a[1]), "r"(a[2]), "r"(a[3]), "r"(b[0]), "r"(b[1]));
}

// ---------------------------------------------------------------------------
// A-resident GEMM (NT): C[r,c] = scale * sum_k A[r,k]*B[c,k] (+bias[c]).
// A slab in SMEM once; CTA loops nTiles n-tiles of 128 cols; 3-stage cp.async
// pipeline stages B chunks 128 x 64k (row 144 B, ldsm conflict-free).
// 512 threads, 16 warps (4m x 4n), warp tile (MI*16) x 32.
// ks loop FULLY UNROLLED in the hot path -> cross-kstep ILP (ldsm of next
// kstep overlaps MMAs of current; A-ldsm have no stage dependency at all).
// Proj fusion: if Ah2 != null, blockIdx.z selects {A,B,bias,Cout} set.
// REQUIRES K%16==0, M%MTILE==0, 16B-aligned rows.
// ---------------------------------------------------------------------------
#define BROW_B  144                    // 128B data (64 halves) + 16B pad
#define B_TILE  (128 * BROW_B)         // 18432
#define NSTAGE  3

template<int MI>
__global__ void __launch_bounds__(512)
gemm_ar_kernel(const __half* __restrict__ Ah, const __half* __restrict__ Ah2,
               const __half* __restrict__ Bh, const __half* __restrict__ Bh2,
               const float* __restrict__ bias, const float* __restrict__ bias2,
               float* __restrict__ Cf, __half* __restrict__ Ch, __half* __restrict__ Ch2,
               int M, int N, int K, int ldc, int nTiles,
               long long sA, long long sB, long long sC, float scale)
{
    constexpr int MTILE = MI * 64;
    extern __shared__ __align__(128) char smem[];
    uint32_t smem_base = smem_to_u32(smem);
    int tid = threadIdx.x;
    int wid = tid >> 5, lane = tid & 31;
    int wm = wid & 3, wn = wid >> 2;              // 4m x 4n
    int z = blockIdx.z;
    int rowBase = blockIdx.x * MTILE;
    int colBase0 = blockIdx.y * (nTiles * 128);

    const int strideA = K * 2 + 16;               // bytes, %16==0
    const uint32_t aSize = (uint32_t)MTILE * strideA;
    const int segsPerRow = K >> 3;

    const __half* pA;
    const __half* pB;
    const float* pb;
    float* pCf;
    __half* pCh;
    if (Ah2) {                                    // fused operand-set select
        pA  = z ? Ah2 : Ah;
        pB  = z ? Bh2 : Bh;
        pb  = z ? bias2 : bias;
        pCh = z ? Ch2 : Ch;
        pCf = nullptr;
    } else {
        pA  = Ah + (size_t)z * sA;
        pB  = Bh + (size_t)z * sB;
        pb  = bias;
        pCf = Cf ? Cf + (size_t)z * sC : nullptr;
        pCh = Ch ? Ch + (size_t)z * sC : nullptr;
    }

    // ---- Load A slab into SMEM (one group) ----
    {
        int total = MTILE * segsPerRow;
        for (int s = tid; s < total; s += 512) {
            int r = s / segsPerRow, cs = s - r * segsPerRow;
            cp_async16(smem_base + (uint32_t)r * strideA + cs * 16,
                       pA + (size_t)(rowBase + r) * K + cs * 8);
        }
        CP_COMMIT();
    }

    int nChunks = (K + 63) >> 6;

    auto prefB = [&](int c, int stage, int colBase) {
        int k0 = c << 6;
        int ksegs = (K - k0) >> 3;                // up to 8
        if (ksegs > 8) ksegs = 8;
        uint32_t sb = smem_base + aSize + stage * B_TILE;
#pragma unroll
        for (int i = 0; i < 2; i++) {
            int s = tid + i * 512;                // 0..1023: 128 rows x 8 segs
            int r = s >> 3, cs = s & 7;
            int bRow = colBase + r;
            if (bRow < N && cs < ksegs)
                cp_async16(sb + r * BROW_B + cs * 16,
                           pB + (size_t)bRow * K + k0 + cs * 8);
        }
    };

#pragma unroll 1
    for (int nt = 0; nt < nTiles; nt++) {
        int colBase = colBase0 + nt * 128;
        int rem = N - colBase - wn * 32;
        int nCap = rem >= 32 ? 4 : (rem <= 0 ? 0 : ((rem + 7) >> 3));

        float acc[MI][4][4];
#pragma unroll
        for (int mi = 0; mi < MI; mi++)
#pragma unroll
            for (int ni = 0; ni < 4; ni++)
#pragma unroll
                for (int j = 0; j < 4; j++) acc[mi][ni][j] = 0.f;

        prefB(0, 0, colBase); CP_COMMIT();
        if (nChunks > 1) prefB(1, 1, colBase);
        CP_COMMIT();

        // one kstep of fragment loads + MMAs (A-ldsm have no stage dependency)
        auto kbody = [&](uint32_t sbB, int kstep, int ks) {
            uint32_t ah[MI][4], bcur[4][2];
#pragma unroll
            for (int mi = 0; mi < MI; mi++) {
                uint32_t addr = smem_base +
                    (uint32_t)((wm * (MI * 16) + mi * 16 + (lane & 15)) * strideA)
                    + ((lane >> 4) * 16) + kstep * 32;
                ldsm_x4(ah[mi], addr);
            }
#pragma unroll
            for (int g = 0; g < 2; g++) {
                if (g * 2 < nCap) {
                    int j = lane & 7, grp = lane >> 3;
                    uint32_t addr = sbB +
                        (uint32_t)((wn * 32 + g * 16 + ((grp >> 1) * 8) + j) * BROW_B
                                   + ((grp & 1) * 16) + ks * 32);
                    uint32_t r[4];
                    ldsm_x4(r, addr);
                    bcur[2*g][0] = r[0]; bcur[2*g][1] = r[1];
                    bcur[2*g+1][0] = r[2]; bcur[2*g+1][1] = r[3];
                }
            }
#pragma unroll
            for (int mi = 0; mi < MI; mi++)
#pragma unroll
                for (int ni = 0; ni < 4; ni++)
                    if (ni < nCap) mma16816h(acc[mi][ni], ah[mi], bcur[ni]);
        };

#pragma unroll 1
        for (int c = 0; c < nChunks; c++) {
            int st = c % 3;
            if (c + 2 < nChunks) prefB(c + 2, (c + 2) % 3, colBase);
            CP_COMMIT();
            CP_WAIT(2);
            __syncthreads();

            int ksMax = (K - (c << 6)) >> 4;      // up to 4
            if (ksMax > 4) ksMax = 4;
            uint32_t sbB = smem_base + aSize + st * B_TILE;
            if (ksMax == 4) {
#pragma unroll
                for (int ks = 0; ks < 4; ks++)
                    kbody(sbB, c * 4 + ks, ks);
            } else {
#pragma unroll 1
                for (int ks = 0; ks < ksMax; ks++)
                    kbody(sbB, c * 4 + ks, ks);
            }
            __syncthreads();
        }

        // Epilogue for this n-tile
#pragma unroll
        for (int mi = 0; mi < MI; mi++) {
#pragma unroll
            for (int ni = 0; ni < 4; ni++) {
#pragma unroll
                for (int half = 0; half < 2; half++) {
                    int gm = rowBase + wm * (MI * 16) + mi * 16 + (lane >> 2) + half * 8;
                    int gn = colBase + wn * 32 + ni * 8 + 2 * (lane & 3);
                    if (gn >= ldc) continue;
                    size_t o = (size_t)gm * ldc + gn;
                    if (gn < N) {
                        float v0 = acc[mi][ni][2*half]   * scale;
                        float v1 = acc[mi][ni][2*half+1] * scale;
                        if (pb) { v0 += pb[gn]; v1 += (gn + 1 < N) ? pb[gn+1] : 0.f; }
                        bool ok1 = (gn + 1 < N);
                        if (pCf) {
                            pCf[o] = v0;
                            if (ok1) pCf[o+1] = v1;
                        }
                        if (pCh) {
                            pCh[o] = __float2half(v0);
                            if (ok1) pCh[o+1] = __float2half(v1);
                            else if (gn + 1 < ldc) pCh[o+1] = __float2half(0.f);
                        }
                    } else if (pCh) {
                        pCh[o] = __float2half(0.f);
                        if (gn + 1 < ldc) pCh[o+1] = __float2half(0.f);
                    }
                }
            }
        }
        CP_WAIT(0);
        __syncthreads();
    }
}

// ---------------------------------------------------------------------------
// Fused pair conversion: fp32 [rows x kin] -> fp16 [rows x kout], pad zero.
// ---------------------------------------------------------------------------
__global__ void cvt_pad2_kernel(const float* __restrict__ x0, const float* __restrict__ x1,
                                __half* __restrict__ h0, __half* __restrict__ h1,
                                int rows, int kin, int kout)
{
    const float* x = blockIdx.y ? x1 : x0;
    __half* h = blockIdx.y ? h1 : h0;
    int q = kout >> 2;
    int i4 = blockIdx.x * blockDim.x + threadIdx.x;
    if (i4 >= rows * q) return;
    int r = i4 / q, c = (i4 - r * q) << 2;
    __half hv[4];
    if (c < kin) {
        float4 v = *(const float4*)(x + (size_t)r * kin + c);
        hv[0] = __float2half(v.x); hv[1] = __float2half(v.y);
        hv[2] = __float2half(v.z); hv[3] = __float2half(v.w);
    } else {
        __half zz = __float2half(0.f);
        hv[0]=hv[1]=hv[2]=hv[3]=zz;
    }
    size_t o = (size_t)r * kout + c;
    h[o]=hv[0]; h[o+1]=hv[1]; h[o+2]=hv[2]; h[o+3]=hv[3];
}

// concepts [b][m][300] -> ct [b][d][512] fp16
__global__ void transpose_h_kernel(const float* __restrict__ in, __half* __restrict__ oh)
{
    __shared__ float t[32][33];
    int b = blockIdx.z;
    int dBase = blockIdx.x * 32, mBase = blockIdx.y * 32;
    int tx = threadIdx.x, ty = threadIdx.y;
#pragma unroll
    for (int i = 0; i < 4; i++) {
        int m = mBase + ty + i * 8, d = dBase + tx;
        if (d < DS) t[ty + i * 8][tx] = in[((size_t)b * NS + m) * DS + d];
    }
    __syncthreads();
#pragma unroll
    for (int i = 0; i < 4; i++) {
        int d = dBase + ty + i * 8, m = mBase + tx;
        if (d < DS)
            oh[((size_t)b * DS + d) * NS + m] = __float2half(t[tx][ty + i * 8]);
    }
}

// ---------------------------------------------------------------------------
// Row softmax over N=512, output fp16 probs
// ---------------------------------------------------------------------------
__global__ void softmax_h_kernel(const float* __restrict__ A, __half* __restrict__ Ph)
{
    __shared__ float sh[4];
    int row = blockIdx.x;
    const float* a = A + (size_t)row * NS;
    int tid = threadIdx.x;

    float v0 = a[tid], v1 = a[tid + 128], v2 = a[tid + 256], v3 = a[tid + 384];
    float mx = fmaxf(fmaxf(v0, v1), fmaxf(v2, v3));
#pragma unroll
    for (int o = 16; o > 0; o >>= 1) mx = fmaxf(mx, __shfl_xor_sync(0xffffffffu, mx, o));
    if ((tid & 31) == 0) sh[tid >> 5] = mx;
    __syncthreads();
    mx = fmaxf(fmaxf(sh[0], sh[1]), fmaxf(sh[2], sh[3]));
    __syncthreads();

    v0 = expf(v0 - mx); v1 = expf(v1 - mx); v2 = expf(v2 - mx); v3 = expf(v3 - mx);
    float s = v0 + v1 + v2 + v3;
#pragma unroll
    for (int o = 16; o > 0; o >>= 1) s += __shfl_xor_sync(0xffffffffu, s, o);
    if ((tid & 31) == 0) sh[tid >> 5] = s;
    __syncthreads();
    s = sh[0] + sh[1] + sh[2] + sh[3];

    float inv = 1.0f / s;
    size_t base = (size_t)row * NS;
    Ph[base + tid]       = __float2half(v0 * inv);
    Ph[base + tid + 128] = __float2half(v1 * inv);
    Ph[base + tid + 256] = __float2half(v2 * inv);
    Ph[base + tid + 384] = __float2half(v3 * inv);
}

// ---------------------------------------------------------------------------
// Mask fill + residual + LayerNorm (verified since R2)
// ---------------------------------------------------------------------------
__global__ void epilogue_kernel(const float* __restrict__ sem, const float* __restrict__ ocr,
                                const int* __restrict__ mask,
                                const float* __restrict__ lnw, const float* __restrict__ lnb,
                                float* __restrict__ out)
{
    __shared__ float sh[4];
    int row = blockIdx.x;
    int tid = threadIdx.x;
    float* y = out + (size_t)row * DS;

    if (mask[row] == 0) {
        for (int i = tid; i < DS; i += 128)
            y[i] = MASKED_CNORM * lnw[i] + lnb[i];
        return;
    }

    const float* o = ocr + (size_t)row * DS;
    const float* s = sem + (size_t)row * DS;

    float x0 = o[tid]       + s[tid];
    float x1 = o[tid + 128] + s[tid + 128];
    float x2 = 0.f;
    float sum = x0 + x1;
    if (tid < 44) { x2 = o[tid + 256] + s[tid + 256]; sum += x2; }

#pragma unroll
    for (int oo = 16; oo > 0; oo >>= 1) sum += __shfl_xor_sync(0xffffffffu, sum, oo);
    if ((tid & 31) == 0) sh[tid >> 5] = sum;
    __syncthreads();
    sum = sh[0] + sh[1] + sh[2] + sh[3];
    __syncthreads();

    float mu = sum * (1.0f / 300.0f);
    float d0 = x0 - mu, d1 = x1 - mu, d2 = (tid < 44) ? (x2 - mu) : 0.f;
    float vs = d0 * d0 + d1 * d1 + d2 * d2;
#pragma unroll
    for (int oo = 16; oo > 0; oo >>= 1) vs += __shfl_xor_sync(0xffffffffu, vs, oo);
    if ((tid & 31) == 0) sh[tid >> 5] = vs;
    __syncthreads();
    vs = sh[0] + sh[1] + sh[2] + sh[3];

    float inv = rsqrtf(vs * (1.0f / 300.0f) + 1e-5f);
    y[tid]       = d0 * inv * lnw[tid]       + lnb[tid];
    y[tid + 128] = d1 * inv * lnw[tid + 128] + lnb[tid + 128];
    if (tid < 44)
        y[tid + 256] = d2 * inv * lnw[tid + 256] + lnb[tid + 256];
}

// ---------------------------------------------------------------------------
extern "C" void kernel_launch(void* const* d_in, const int* in_sizes, int n_in,
                              void* d_out, int out_size)
{
    const float* concepts = (const float*)d_in[0];
    const float* ocr      = (const float*)d_in[1];
    const int*   mask     = (const int*)d_in[2];
    const float* wq       = (const float*)d_in[3];
    const float* bq       = (const float*)d_in[4];
    const float* wk       = (const float*)d_in[5];
    const float* bk       = (const float*)d_in[6];
    const float* lnw      = (const float*)d_in[7];
    const float* lnb      = (const float*)d_in[8];
    float* out = (float*)d_out;

    const int SM4 = 256 * (DP * 2 + 16) + NSTAGE * B_TILE;   // 215040
    const int SM2 = 128 * (NS * 2 + 16) + NSTAGE * B_TILE;   // 188416
    cudaFuncSetAttribute(gemm_ar_kernel<4>, cudaFuncAttributeMaxDynamicSharedMemorySize, SM4);
    cudaFuncSetAttribute(gemm_ar_kernel<2>, cudaFuncAttributeMaxDynamicSharedMemorySize, SM2);

    __half *c_h, *o_h, *ct_h, *wqh, *wkh, *Qh, *Kh, *Ph;
    float *A, *S;
    cudaGetSymbolAddress((void**)&c_h, g_c_h);
    cudaGetSymbolAddress((void**)&o_h, g_o_h);
    cudaGetSymbolAddress((void**)&ct_h, g_ct_h);
    cudaGetSymbolAddress((void**)&wqh, g_wq_h);
    cudaGetSymbolAddress((void**)&wkh, g_wk_h);
    cudaGetSymbolAddress((void**)&Qh, g_Qh);
    cudaGetSymbolAddress((void**)&Kh, g_Kh);
    cudaGetSymbolAddress((void**)&Ph, g_Ph);
    cudaGetSymbolAddress((void**)&A, g_A);
    cudaGetSymbolAddress((void**)&S, g_S);

    // fp16 conversions (padded [.. x 304]); fused pairs via grid.y
    {
        int t1 = BN_ROWS * (DP / 4);
        cvt_pad2_kernel<<<dim3((t1 + 255) / 256, 2), 256>>>(
            concepts, ocr, c_h, o_h, BN_ROWS, DS, DP);
        int t2 = DS * (DP / 4);
        cvt_pad2_kernel<<<dim3((t2 + 255) / 256, 2), 256>>>(
            wq, wk, wqh, wkh, DS, DS, DP);
        dim3 tg((DS + 31) / 32, NS / 32, BB);
        transpose_h_kernel<<<tg, dim3(32, 8)>>>(concepts, ct_h);
    }

    // Fused projections: z=0: Q = concepts@wq^T+bq ; z=1: K = ocr@wk^T+bk (fp16, ldc=304)
    gemm_ar_kernel<4><<<dim3(BN_ROWS / 256, 1, 2), 512, SM4>>>(
        c_h, o_h, wqh, wkh, bq, bk, nullptr, Qh, Kh,
        BN_ROWS, DS, DP, DP, /*nTiles=*/3, 0, 0, 0, 1.0f);

    // scores[b] = (Q K^T)/sqrt(D)  fp32, one CTA covers full N via 4 inner n-tiles
    gemm_ar_kernel<4><<<dim3(NS / 256, 1, BB), 512, SM4>>>(
        Qh, nullptr, Kh, nullptr, nullptr, nullptr, A, nullptr, nullptr,
        NS, NS, DP, NS, /*nTiles=*/4,
        (long long)NS * DP, (long long)NS * DP, (long long)NS * NS, INV_SQRT_D);

    // softmax -> P fp16
    softmax_h_kernel<<<BN_ROWS, 128>>>(A, Ph);

    // sem[b] = P @ concepts[b]  (B = concepts^T, K=512), MTILE=128, 3 inner n-tiles
    gemm_ar_kernel<2><<<dim3(NS / 128, 1, BB), 512, SM2>>>(
        Ph, nullptr, ct_h, nullptr, nullptr, nullptr, S, nullptr, nullptr,
        NS, DS, NS, DS, /*nTiles=*/3,
        (long long)NS * NS, (long long)DS * NS, (long long)NS * DS, 1.0f);

    // mask + residual + LayerNorm
    epilogue_kernel<<<BN_ROWS, 128>>>(S, ocr, mask, lnw, lnb, out);

    (void)in_sizes; (void)n_in; (void)out_size;
}

// round 17
// speedup vs baseline: 1.0265x; 1.0265x over previous
#include <cuda_runtime.h>
#include <cuda_fp16.h>
#include <cstdint>

#define BB 64
#define NS 512
#define DS 300
#define DP 304                          // K padded to multiple of 16
#define BN_ROWS (BB*NS)                 // 32768
#define INV_SQRT_D 0.057735026918962576f
#define MASKED_CNORM (1.0f)

// ---------------------------------------------------------------------------
// Device-global scratch (runtime allocation forbidden); 16B-aligned rows.
// ---------------------------------------------------------------------------
__device__ alignas(1024) __half g_c_h[(size_t)BN_ROWS * DP];     // concepts fp16
__device__ alignas(1024) __half g_o_h[(size_t)BN_ROWS * DP];     // ocr fp16
__device__ alignas(1024) __half g_ct_h[(size_t)BB * DS * NS];    // concepts^T fp16
__device__ alignas(1024) __half g_wq_h[DS * DP];
__device__ alignas(1024) __half g_wk_h[DS * DP];
__device__ alignas(1024) __half g_Qh[(size_t)BN_ROWS * DP];
__device__ alignas(1024) __half g_Kh[(size_t)BN_ROWS * DP];
__device__ alignas(1024) __half g_Ph[(size_t)BB * NS * NS];
__device__ alignas(1024) float  g_A[(size_t)BB * NS * NS];       // scores fp32
__device__ alignas(1024) float  g_S[(size_t)BN_ROWS * DS];       // semantic fp32

// ---------------------------------------------------------------------------
// PTX helpers (sm_80-era only; compiles under compute_103)
// ---------------------------------------------------------------------------
__device__ __forceinline__ uint32_t smem_to_u32(const void* p) {
    uint32_t a;
    asm("{ .reg .u64 t; cvta.to.shared.u64 t, %1; cvt.u32.u64 %0, t; }" : "=r"(a) : "l"(p));
    return a;
}
__device__ __forceinline__ void cp_async16(uint32_t dst, const void* src) {
    asm volatile("cp.async.cg.shared.global [%0], [%1], 16;"
                 :: "r"(dst), "l"(src) : "memory");
}
#define CP_COMMIT() asm volatile("cp.async.commit_group;" ::: "memory")
#define CP_WAIT(n)  asm volatile("cp.async.wait_group %0;" :: "n"(n) : "memory")

__device__ __forceinline__ void ldsm_x4(uint32_t* r, uint32_t addr) {
    asm volatile("ldmatrix.sync.aligned.m8n8.x4.shared.b16 {%0,%1,%2,%3}, [%4];"
                 : "=r"(r[0]), "=r"(r[1]), "=r"(r[2]), "=r"(r[3]) : "r"(addr));
}
__device__ __forceinline__ void mma16816h(float* d, const uint32_t* a, const uint32_t* b) {
    asm volatile("mma.sync.aligned.m16n8k16.row.col.f32.f16.f16.f32 "
                 "{%0,%1,%2,%3}, {%4,%5,%6,%7}, {%8,%9}, {%0,%1,%2,%3};"
                 : "+f"(d[0]), "+f"(d[1]), "+f"(d[2]), "+f"(d[3])
                 : "r"(a[0]), "r"(a[1]), "r"(a[2]), "r"(a[3]), "r"(b[0]), "r"(b[1]));
}

// ---------------------------------------------------------------------------
// A-resident GEMM (NT): C[r,c] = scale * sum_k A[r,k]*B[c,k] (+bias[c]).
// A slab (MTILE x K) in SMEM once; CTA loops nTiles n-tiles of 128 cols with a
// 3-stage cp.async B pipeline (BK k per chunk). Warps: (TPB/32) = 4m x (TPB/128)n,
// warp tile (MI*16) x (NI*8). Per-warp nCap trims to true N.
// BK=32 -> B row 80 B; BK=64 -> 144 B (both ldsm conflict-free).
// MINB: min CTAs/SM hint (2 for the small-smem variant -> regs capped at 128,
// two independent CTAs per SM decouple barrier/scoreboard phases).
// Proj fusion: if Ah2 != null, blockIdx.z selects {A,B,bias,Cout} set.
// REQUIRES K%16==0, M%MTILE==0, 16B-aligned rows.
// ---------------------------------------------------------------------------
#define NSTAGE  3

template<int MI, int NI, int TPB, int BK, int MINB>
__global__ void __launch_bounds__(TPB, MINB)
gemm_ar_kernel(const __half* __restrict__ Ah, const __half* __restrict__ Ah2,
               const __half* __restrict__ Bh, const __half* __restrict__ Bh2,
               const float* __restrict__ bias, const float* __restrict__ bias2,
               float* __restrict__ Cf, __half* __restrict__ Ch, __half* __restrict__ Ch2,
               int M, int N, int K, int ldc, int nTiles,
               long long sA, long long sB, long long sC, float scale)
{
    constexpr int MTILE = MI * 64;
    constexpr int BROW = (BK == 64) ? 144 : 80;
    constexpr int BT = 128 * BROW;
    constexpr int BSEGS = BK / 8;                 // 16B segs per B row
    constexpr int KSPC = BK / 16;                 // ksteps per chunk
    extern __shared__ __align__(128) char smem[];
    uint32_t smem_base = smem_to_u32(smem);
    int tid = threadIdx.x;
    int wid = tid >> 5, lane = tid & 31;
    int wm = wid & 3, wn = wid >> 2;
    int z = blockIdx.z;
    int rowBase = blockIdx.x * MTILE;
    int colBase0 = blockIdx.y * (nTiles * 128);

    const int strideA = K * 2 + 16;               // bytes, %16==0
    const uint32_t aSize = (uint32_t)MTILE * strideA;
    const int segsPerRow = K >> 3;

    const __half* pA;
    const __half* pB;
    const float* pb;
    float* pCf;
    __half* pCh;
    if (Ah2) {                                    // fused operand-set select
        pA  = z ? Ah2 : Ah;
        pB  = z ? Bh2 : Bh;
        pb  = z ? bias2 : bias;
        pCh = z ? Ch2 : Ch;
        pCf = nullptr;
    } else {
        pA  = Ah + (size_t)z * sA;
        pB  = Bh + (size_t)z * sB;
        pb  = bias;
        pCf = Cf ? Cf + (size_t)z * sC : nullptr;
        pCh = Ch ? Ch + (size_t)z * sC : nullptr;
    }

    // ---- Load A slab into SMEM (one group) ----
    {
        int total = MTILE * segsPerRow;
        for (int s = tid; s < total; s += TPB) {
            int r = s / segsPerRow, cs = s - r * segsPerRow;
            cp_async16(smem_base + (uint32_t)r * strideA + cs * 16,
                       pA + (size_t)(rowBase + r) * K + cs * 8);
        }
        CP_COMMIT();
    }

    int nChunks = (K + BK - 1) / BK;

    auto prefB = [&](int c, int stage, int colBase) {
        int k0 = c * BK;
        int ksegs = (K - k0) >> 3;
        if (ksegs > BSEGS) ksegs = BSEGS;
        uint32_t sb = smem_base + aSize + stage * BT;
#pragma unroll
        for (int i = 0; i < (128 * BSEGS + TPB - 1) / TPB; i++) {
            int s = tid + i * TPB;
            if (s < 128 * BSEGS) {
                int r = s / BSEGS, cs = s - r * BSEGS;
                int bRow = colBase + r;
                if (bRow < N && cs < ksegs)
                    cp_async16(sb + r * BROW + cs * 16,
                               pB + (size_t)bRow * K + k0 + cs * 8);
            }
        }
    };

#pragma unroll 1
    for (int nt = 0; nt < nTiles; nt++) {
        int colBase = colBase0 + nt * 128;
        int rem = N - colBase - wn * (NI * 8);
        int nCap = rem >= NI * 8 ? NI : (rem <= 0 ? 0 : ((rem + 7) >> 3));

        float acc[MI][NI][4];
#pragma unroll
        for (int mi = 0; mi < MI; mi++)
#pragma unroll
            for (int ni = 0; ni < NI; ni++)
#pragma unroll
                for (int j = 0; j < 4; j++) acc[mi][ni][j] = 0.f;

        prefB(0, 0, colBase); CP_COMMIT();
        if (nChunks > 1) prefB(1, 1, colBase);
        CP_COMMIT();

        auto kbody = [&](uint32_t sbB, int kstep, int ks) {
            uint32_t ah[MI][4], bcur[NI][2];
#pragma unroll
            for (int mi = 0; mi < MI; mi++) {
                uint32_t addr = smem_base +
                    (uint32_t)((wm * (MI * 16) + mi * 16 + (lane & 15)) * strideA)
                    + ((lane >> 4) * 16) + kstep * 32;
                ldsm_x4(ah[mi], addr);
            }
#pragma unroll
            for (int g = 0; g < NI / 2; g++) {
                if (g * 2 < nCap) {
                    int j = lane & 7, grp = lane >> 3;
                    uint32_t addr = sbB +
                        (uint32_t)((wn * (NI * 8) + g * 16 + ((grp >> 1) * 8) + j) * BROW
                                   + ((grp & 1) * 16) + ks * 32);
                    uint32_t r[4];
                    ldsm_x4(r, addr);
                    bcur[2*g][0] = r[0]; bcur[2*g][1] = r[1];
                    bcur[2*g+1][0] = r[2]; bcur[2*g+1][1] = r[3];
                }
            }
#pragma unroll
            for (int mi = 0; mi < MI; mi++)
#pragma unroll
                for (int ni = 0; ni < NI; ni++)
                    if (ni < nCap) mma16816h(acc[mi][ni], ah[mi], bcur[ni]);
        };

#pragma unroll 1
        for (int c = 0; c < nChunks; c++) {
            int st = c % 3;
            if (c + 2 < nChunks) prefB(c + 2, (c + 2) % 3, colBase);
            CP_COMMIT();
            CP_WAIT(2);
            __syncthreads();

            int ksMax = (K - c * BK) >> 4;
            if (ksMax > KSPC) ksMax = KSPC;
            uint32_t sbB = smem_base + aSize + st * BT;
            if (ksMax == KSPC) {
#pragma unroll
                for (int ks = 0; ks < KSPC; ks++)
                    kbody(sbB, c * KSPC + ks, ks);
            } else {
#pragma unroll 1
                for (int ks = 0; ks < ksMax; ks++)
                    kbody(sbB, c * KSPC + ks, ks);
            }
            __syncthreads();
        }

        // Epilogue for this n-tile
#pragma unroll
        for (int mi = 0; mi < MI; mi++) {
#pragma unroll
            for (int ni = 0; ni < NI; ni++) {
#pragma unroll
                for (int half = 0; half < 2; half++) {
                    int gm = rowBase + wm * (MI * 16) + mi * 16 + (lane >> 2) + half * 8;
                    int gn = colBase + wn * (NI * 8) + ni * 8 + 2 * (lane & 3);
                    if (gn >= ldc) continue;
                    size_t o = (size_t)gm * ldc + gn;
                    if (gn < N) {
                        float v0 = acc[mi][ni][2*half]   * scale;
                        float v1 = acc[mi][ni][2*half+1] * scale;
                        if (pb) { v0 += pb[gn]; v1 += (gn + 1 < N) ? pb[gn+1] : 0.f; }
                        bool ok1 = (gn + 1 < N);
                        if (pCf) {
                            pCf[o] = v0;
                            if (ok1) pCf[o+1] = v1;
                        }
                        if (pCh) {
                            pCh[o] = __float2half(v0);
                            if (ok1) pCh[o+1] = __float2half(v1);
                            else if (gn + 1 < ldc) pCh[o+1] = __float2half(0.f);
                        }
                    } else if (pCh) {
                        pCh[o] = __float2half(0.f);
                        if (gn + 1 < ldc) pCh[o+1] = __float2half(0.f);
                    }
                }
            }
        }
        CP_WAIT(0);
        __syncthreads();
    }
}

// ---------------------------------------------------------------------------
// Fused pair conversion: fp32 [rows x kin] -> fp16 [rows x kout], pad zero.
// ---------------------------------------------------------------------------
__global__ void cvt_pad2_kernel(const float* __restrict__ x0, const float* __restrict__ x1,
                                __half* __restrict__ h0, __half* __restrict__ h1,
                                int rows, int kin, int kout)
{
    const float* x = blockIdx.y ? x1 : x0;
    __half* h = blockIdx.y ? h1 : h0;
    int q = kout >> 2;
    int i4 = blockIdx.x * blockDim.x + threadIdx.x;
    if (i4 >= rows * q) return;
    int r = i4 / q, c = (i4 - r * q) << 2;
    __half hv[4];
    if (c < kin) {
        float4 v = *(const float4*)(x + (size_t)r * kin + c);
        hv[0] = __float2half(v.x); hv[1] = __float2half(v.y);
        hv[2] = __float2half(v.z); hv[3] = __float2half(v.w);
    } else {
        __half zz = __float2half(0.f);
        hv[0]=hv[1]=hv[2]=hv[3]=zz;
    }
    size_t o = (size_t)r * kout + c;
    h[o]=hv[0]; h[o+1]=hv[1]; h[o+2]=hv[2]; h[o+3]=hv[3];
}

// concepts [b][m][300] -> ct [b][d][512] fp16
__global__ void transpose_h_kernel(const float* __restrict__ in, __half* __restrict__ oh)
{
    __shared__ float t[32][33];
    int b = blockIdx.z;
    int dBase = blockIdx.x * 32, mBase = blockIdx.y * 32;
    int tx = threadIdx.x, ty = threadIdx.y;
#pragma unroll
    for (int i = 0; i < 4; i++) {
        int m = mBase + ty + i * 8, d = dBase + tx;
        if (d < DS) t[ty + i * 8][tx] = in[((size_t)b * NS + m) * DS + d];
    }
    __syncthreads();
#pragma unroll
    for (int i = 0; i < 4; i++) {
        int d = dBase + ty + i * 8, m = mBase + tx;
        if (d < DS)
            oh[((size_t)b * DS + d) * NS + m] = __float2half(t[tx][ty + i * 8]);
    }
}

// ---------------------------------------------------------------------------
// Row softmax over N=512, output fp16 probs
// ---------------------------------------------------------------------------
__global__ void softmax_h_kernel(const float* __restrict__ A, __half* __restrict__ Ph)
{
    __shared__ float sh[4];
    int row = blockIdx.x;
    const float* a = A + (size_t)row * NS;
    int tid = threadIdx.x;

    float v0 = a[tid], v1 = a[tid + 128], v2 = a[tid + 256], v3 = a[tid + 384];
    float mx = fmaxf(fmaxf(v0, v1), fmaxf(v2, v3));
#pragma unroll
    for (int o = 16; o > 0; o >>= 1) mx = fmaxf(mx, __shfl_xor_sync(0xffffffffu, mx, o));
    if ((tid & 31) == 0) sh[tid >> 5] = mx;
    __syncthreads();
    mx = fmaxf(fmaxf(sh[0], sh[1]), fmaxf(sh[2], sh[3]));
    __syncthreads();

    v0 = expf(v0 - mx); v1 = expf(v1 - mx); v2 = expf(v2 - mx); v3 = expf(v3 - mx);
    float s = v0 + v1 + v2 + v3;
#pragma unroll
    for (int o = 16; o > 0; o >>= 1) s += __shfl_xor_sync(0xffffffffu, s, o);
    if ((tid & 31) == 0) sh[tid >> 5] = s;
    __syncthreads();
    s = sh[0] + sh[1] + sh[2] + sh[3];

    float inv = 1.0f / s;
    size_t base = (size_t)row * NS;
    Ph[base + tid]       = __float2half(v0 * inv);
    Ph[base + tid + 128] = __float2half(v1 * inv);
    Ph[base + tid + 256] = __float2half(v2 * inv);
    Ph[base + tid + 384] = __float2half(v3 * inv);
}

// ---------------------------------------------------------------------------
// Mask fill + residual + LayerNorm (verified since R2)
// ---------------------------------------------------------------------------
__global__ void epilogue_kernel(const float* __restrict__ sem, const float* __restrict__ ocr,
                                const int* __restrict__ mask,
                                const float* __restrict__ lnw, const float* __restrict__ lnb,
                                float* __restrict__ out)
{
    __shared__ float sh[4];
    int row = blockIdx.x;
    int tid = threadIdx.x;
    float* y = out + (size_t)row * DS;

    if (mask[row] == 0) {
        for (int i = tid; i < DS; i += 128)
            y[i] = MASKED_CNORM * lnw[i] + lnb[i];
        return;
    }

    const float* o = ocr + (size_t)row * DS;
    const float* s = sem + (size_t)row * DS;

    float x0 = o[tid]       + s[tid];
    float x1 = o[tid + 128] + s[tid + 128];
    float x2 = 0.f;
    float sum = x0 + x1;
    if (tid < 44) { x2 = o[tid + 256] + s[tid + 256]; sum += x2; }

#pragma unroll
    for (int oo = 16; oo > 0; oo >>= 1) sum += __shfl_xor_sync(0xffffffffu, sum, oo);
    if ((tid & 31) == 0) sh[tid >> 5] = sum;
    __syncthreads();
    sum = sh[0] + sh[1] + sh[2] + sh[3];
    __syncthreads();

    float mu = sum * (1.0f / 300.0f);
    float d0 = x0 - mu, d1 = x1 - mu, d2 = (tid < 44) ? (x2 - mu) : 0.f;
    float vs = d0 * d0 + d1 * d1 + d2 * d2;
#pragma unroll
    for (int oo = 16; oo > 0; oo >>= 1) vs += __shfl_xor_sync(0xffffffffu, vs, oo);
    if ((tid & 31) == 0) sh[tid >> 5] = vs;
    __syncthreads();
    vs = sh[0] + sh[1] + sh[2] + sh[3];

    float inv = rsqrtf(vs * (1.0f / 300.0f) + 1e-5f);
    y[tid]       = d0 * inv * lnw[tid]       + lnb[tid];
    y[tid + 128] = d1 * inv * lnw[tid + 128] + lnb[tid + 128];
    if (tid < 44)
        y[tid + 256] = d2 * inv * lnw[tid + 256] + lnb[tid + 256];
}

// ---------------------------------------------------------------------------
extern "C" void kernel_launch(void* const* d_in, const int* in_sizes, int n_in,
                              void* d_out, int out_size)
{
    const float* concepts = (const float*)d_in[0];
    const float* ocr      = (const float*)d_in[1];
    const int*   mask     = (const int*)d_in[2];
    const float* wq       = (const float*)d_in[3];
    const float* bq       = (const float*)d_in[4];
    const float* wk       = (const float*)d_in[5];
    const float* bk       = (const float*)d_in[6];
    const float* lnw      = (const float*)d_in[7];
    const float* lnb      = (const float*)d_in[8];
    float* out = (float*)d_out;

    // Variants:
    //  small: MI=2,NI=8,TPB=256,BK=32,MINB=2 -> smem 128*624 + 3*10240 = 110592 (2 CTAs/SM)
    //  pv   : MI=2,NI=4,TPB=512,BK=64,MINB=1 -> smem 128*1040 + 3*18432 = 188416
    const int SM_SMALL = 128 * (DP * 2 + 16) + 3 * (128 * 80);    // 110592
    const int SM_PV    = 128 * (NS * 2 + 16) + 3 * (128 * 144);   // 188416
    cudaFuncSetAttribute((const void*)gemm_ar_kernel<2, 8, 256, 32, 2>,
                         cudaFuncAttributeMaxDynamicSharedMemorySize, SM_SMALL);
    cudaFuncSetAttribute((const void*)gemm_ar_kernel<2, 4, 512, 64, 1>,
                         cudaFuncAttributeMaxDynamicSharedMemorySize, SM_PV);

    __half *c_h, *o_h, *ct_h, *wqh, *wkh, *Qh, *Kh, *Ph;
    float *A, *S;
    cudaGetSymbolAddress((void**)&c_h, g_c_h);
    cudaGetSymbolAddress((void**)&o_h, g_o_h);
    cudaGetSymbolAddress((void**)&ct_h, g_ct_h);
    cudaGetSymbolAddress((void**)&wqh, g_wq_h);
    cudaGetSymbolAddress((void**)&wkh, g_wk_h);
    cudaGetSymbolAddress((void**)&Qh, g_Qh);
    cudaGetSymbolAddress((void**)&Kh, g_Kh);
    cudaGetSymbolAddress((void**)&Ph, g_Ph);
    cudaGetSymbolAddress((void**)&A, g_A);
    cudaGetSymbolAddress((void**)&S, g_S);

    // fp16 conversions (padded [.. x 304]); fused pairs via grid.y
    {
        int t1 = BN_ROWS * (DP / 4);
        cvt_pad2_kernel<<<dim3((t1 + 255) / 256, 2), 256>>>(
            concepts, ocr, c_h, o_h, BN_ROWS, DS, DP);
        int t2 = DS * (DP / 4);
        cvt_pad2_kernel<<<dim3((t2 + 255) / 256, 2), 256>>>(
            wq, wk, wqh, wkh, DS, DS, DP);
        dim3 tg((DS + 31) / 32, NS / 32, BB);
        transpose_h_kernel<<<tg, dim3(32, 8)>>>(concepts, ct_h);
    }

    // Fused projections: z=0: Q = concepts@wq^T+bq ; z=1: K = ocr@wk^T+bk (fp16, ldc=304)
    gemm_ar_kernel<2, 8, 256, 32, 2><<<dim3(BN_ROWS / 128, 1, 2), 256, SM_SMALL>>>(
        c_h, o_h, wqh, wkh, bq, bk, nullptr, Qh, Kh,
        BN_ROWS, DS, DP, DP, /*nTiles=*/3, 0, 0, 0, 1.0f);

    // scores[b] = (Q K^T)/sqrt(D)  fp32, CTA covers full N via 4 inner n-tiles
    gemm_ar_kernel<2, 8, 256, 32, 2><<<dim3(NS / 128, 1, BB), 256, SM_SMALL>>>(
        Qh, nullptr, Kh, nullptr, nullptr, nullptr, A, nullptr, nullptr,
        NS, NS, DP, NS, /*nTiles=*/4,
        (long long)NS * DP, (long long)NS * DP, (long long)NS * NS, INV_SQRT_D);

    // softmax -> P fp16
    softmax_h_kernel<<<BN_ROWS, 128>>>(A, Ph);

    // sem[b] = P @ concepts[b]  (B = concepts^T, K=512), MTILE=128, 3 inner n-tiles
    gemm_ar_kernel<2, 4, 512, 64, 1><<<dim3(NS / 128, 1, BB), 512, SM_PV>>>(
        Ph, nullptr, ct_h, nullptr, nullptr, nullptr, S, nullptr, nullptr,
        NS, DS, NS, DS, /*nTiles=*/3,
        (long long)NS * NS, (long long)DS * NS, (long long)NS * DS, 1.0f);

    // mask + residual + LayerNorm
    epilogue_kernel<<<BN_ROWS, 128>>>(S, ocr, mask, lnw, lnb, out);

    (void)in_sizes; (void)n_in; (void)out_size;
}